// round 1
// baseline (speedup 1.0000x reference)
#include <cuda_runtime.h>
#include <math.h>

// ---------------- device globals (scratch; no allocation allowed) ----------
__device__ float  g_min;
__device__ float  g_max;
__device__ double g_sum;

// ---------------- constants -------------------------------------------------
#define IMG_H 512
#define IMG_W 512
#define N_IMG 48            // B*C = 16*3
#define OUT_H 502           // 512 - 10
#define OUT_W 502
#define TS    32            // output tile size
#define HALO  10
#define INT   42            // TS + HALO (input tile span)
#define SXPAD 44            // padded stride for input tiles

struct W11 { float w[11]; };

// ---------------- atomic float min/max helpers ------------------------------
__device__ __forceinline__ void atomicMaxF(float* a, float v) {
    if (v >= 0.0f) atomicMax((int*)a, __float_as_int(v));
    else           atomicMin((unsigned int*)a, __float_as_uint(v));
}
__device__ __forceinline__ void atomicMinF(float* a, float v) {
    if (v >= 0.0f) atomicMin((int*)a, __float_as_int(v));
    else           atomicMax((unsigned int*)a, __float_as_uint(v));
}

// ---------------- kernel 0: init --------------------------------------------
__global__ void init_kernel() {
    g_min = INFINITY;
    g_max = -INFINITY;
    g_sum = 0.0;
}

// ---------------- kernel 1: global min/max of y_pred ------------------------
__global__ void minmax_kernel(const float4* __restrict__ x, int n4) {
    float vmin = INFINITY, vmax = -INFINITY;
    for (int i = blockIdx.x * blockDim.x + threadIdx.x; i < n4;
         i += gridDim.x * blockDim.x) {
        float4 v = x[i];
        vmin = fminf(vmin, fminf(fminf(v.x, v.y), fminf(v.z, v.w)));
        vmax = fmaxf(vmax, fmaxf(fmaxf(v.x, v.y), fmaxf(v.z, v.w)));
    }
    // warp reduce
    #pragma unroll
    for (int o = 16; o > 0; o >>= 1) {
        vmin = fminf(vmin, __shfl_down_sync(0xffffffffu, vmin, o));
        vmax = fmaxf(vmax, __shfl_down_sync(0xffffffffu, vmax, o));
    }
    __shared__ float smin[32], smax[32];
    int lane = threadIdx.x & 31, wid = threadIdx.x >> 5;
    if (lane == 0) { smin[wid] = vmin; smax[wid] = vmax; }
    __syncthreads();
    if (wid == 0) {
        int nw = (blockDim.x + 31) >> 5;
        vmin = (lane < nw) ? smin[lane] : INFINITY;
        vmax = (lane < nw) ? smax[lane] : -INFINITY;
        #pragma unroll
        for (int o = 16; o > 0; o >>= 1) {
            vmin = fminf(vmin, __shfl_down_sync(0xffffffffu, vmin, o));
            vmax = fmaxf(vmax, __shfl_down_sync(0xffffffffu, vmax, o));
        }
        if (lane == 0) { atomicMinF(&g_min, vmin); atomicMaxF(&g_max, vmax); }
    }
}

// ---------------- kernel 2: fused separable SSIM ----------------------------
__global__ __launch_bounds__(1024, 1)
void ssim_kernel(const float* __restrict__ xg, const float* __restrict__ yg,
                 W11 wts) {
    __shared__ float sx[INT][SXPAD];
    __shared__ float sy[INT][SXPAD];
    __shared__ float hx [INT][TS];
    __shared__ float hy [INT][TS];
    __shared__ float hxx[INT][TS];
    __shared__ float hyy[INT][TS];
    __shared__ float hxy[INT][TS];
    __shared__ float warp_part[32];

    const int tid = threadIdx.x;
    const int img = blockIdx.z;
    const int r0  = blockIdx.y * TS;
    const int c0  = blockIdx.x * TS;
    const float* __restrict__ xi = xg + (size_t)img * IMG_H * IMG_W;
    const float* __restrict__ yi = yg + (size_t)img * IMG_H * IMG_W;

    // stage 1: load 42x42 halo tiles (coalesced along rows)
    for (int i = tid; i < INT * INT; i += 1024) {
        int r = i / INT, c = i - r * INT;
        int gr = r0 + r, gc = c0 + c;
        float xv = 0.0f, yv = 0.0f;
        if (gr < IMG_H && gc < IMG_W) {
            int idx = gr * IMG_W + gc;
            xv = xi[idx];
            yv = yi[idx];
        }
        sx[r][c] = xv;
        sy[r][c] = yv;
    }
    __syncthreads();

    // stage 2: horizontal 11-tap blur of {x, y, x^2, y^2, xy} -> 42 x 32
    for (int p = tid; p < INT * TS; p += 1024) {
        int r = p >> 5, c = p & 31;
        float a = 0.f, b = 0.f, cc = 0.f, d = 0.f, e = 0.f;
        #pragma unroll
        for (int k = 0; k < 11; k++) {
            float wk = wts.w[k];
            float xv = sx[r][c + k];
            float yv = sy[r][c + k];
            a  += wk * xv;
            b  += wk * yv;
            cc += wk * xv * xv;
            d  += wk * yv * yv;
            e  += wk * xv * yv;
        }
        hx [r][c] = a;
        hy [r][c] = b;
        hxx[r][c] = cc;
        hyy[r][c] = d;
        hxy[r][c] = e;
    }
    __syncthreads();

    // stage 3: vertical 11-tap blur + SSIM map value
    const int ty = tid >> 5, tx = tid & 31;
    const int orow = r0 + ty, ocol = c0 + tx;
    float ssim = 0.0f;
    if (orow < OUT_H && ocol < OUT_W) {
        float mu1 = 0.f, mu2 = 0.f, mxx = 0.f, myy = 0.f, mxy = 0.f;
        #pragma unroll
        for (int k = 0; k < 11; k++) {
            float wk = wts.w[k];
            mu1 += wk * hx [ty + k][tx];
            mu2 += wk * hy [ty + k][tx];
            mxx += wk * hxx[ty + k][tx];
            myy += wk * hyy[ty + k][tx];
            mxy += wk * hxy[ty + k][tx];
        }
        float L  = g_max - g_min;
        float C1 = (0.01f * L) * (0.01f * L);
        float C2 = (0.03f * L) * (0.03f * L);
        float mu1_sq  = mu1 * mu1;
        float mu2_sq  = mu2 * mu2;
        float mu1_mu2 = mu1 * mu2;
        float s1 = mxx - mu1_sq;
        float s2 = myy - mu2_sq;
        float s12 = mxy - mu1_mu2;
        float v1 = 2.0f * s12 + C2;
        float v2 = s1 + s2 + C2;
        ssim = (2.0f * mu1_mu2 + C1) * v1 / ((mu1_sq + mu2_sq + C1) * v2);
    }

    // block reduction of ssim sum
    #pragma unroll
    for (int o = 16; o > 0; o >>= 1)
        ssim += __shfl_down_sync(0xffffffffu, ssim, o);
    if (tx == 0) warp_part[ty] = ssim;
    __syncthreads();
    if (ty == 0) {
        float v = warp_part[tx];
        #pragma unroll
        for (int o = 16; o > 0; o >>= 1)
            v += __shfl_down_sync(0xffffffffu, v, o);
        if (tx == 0) atomicAdd(&g_sum, (double)v);
    }
}

// ---------------- kernel 3: finalize ----------------------------------------
__global__ void finalize_kernel(float* __restrict__ out) {
    const double n = (double)N_IMG * OUT_H * OUT_W;
    out[0] = (float)(-(g_sum / n));
}

// ---------------- launcher ---------------------------------------------------
extern "C" void kernel_launch(void* const* d_in, const int* in_sizes, int n_in,
                              void* d_out, int out_size) {
    const float* y_pred = (const float*)d_in[0];
    const float* y_true = (const float*)d_in[1];
    float* out = (float*)d_out;

    // gaussian weights (computed on host, exact match to reference recipe)
    W11 wts;
    {
        double g[11], s = 0.0;
        for (int i = 0; i < 11; i++) {
            double x = (double)(i - 5);
            g[i] = exp(-(x * x) / (2.0 * 1.5 * 1.5));
            s += g[i];
        }
        for (int i = 0; i < 11; i++) wts.w[i] = (float)(g[i] / s);
    }

    init_kernel<<<1, 1>>>();

    int n4 = (N_IMG * IMG_H * IMG_W) / 4;   // divisible by 4
    minmax_kernel<<<1024, 256>>>((const float4*)y_pred, n4);

    dim3 grid((OUT_W + TS - 1) / TS, (OUT_H + TS - 1) / TS, N_IMG);
    ssim_kernel<<<grid, 1024>>>(y_pred, y_true, wts);

    finalize_kernel<<<1, 1>>>(out);
}

// round 2
// speedup vs baseline: 3.6136x; 3.6136x over previous
#include <cuda_runtime.h>
#include <math.h>

// ---------------- device globals (scratch; no allocation allowed) ----------
__device__ float  g_min;
__device__ float  g_max;
__device__ double g_sum;

// ---------------- constants -------------------------------------------------
#define IMG_H 512
#define IMG_W 512
#define N_IMG 48            // B*C = 16*3
#define OUT_H 502           // 512 - 10
#define OUT_W 502
#define RSTRIP 64           // output rows per CTA
#define NSTRIPS 8           // ceil(502/64)
#define VBW 528             // padded smem row width (>= 524, 16B-mult)

// Gaussian 11-tap weights for sigma=1.5 (normalized), as literals so ptxas
// emits FFMA-imm (rt_SMSP=1, 2x issue rate vs 3-reg FFMA).
#define GW0 0.00102838f
#define GW1 0.00759877f
#define GW2 0.03600077f
#define GW3 0.10936069f
#define GW4 0.21300553f
#define GW5 0.26601173f

// ---------------- atomic float min/max helpers ------------------------------
__device__ __forceinline__ void atomicMaxF(float* a, float v) {
    if (v >= 0.0f) atomicMax((int*)a, __float_as_int(v));
    else           atomicMin((unsigned int*)a, __float_as_uint(v));
}
__device__ __forceinline__ void atomicMinF(float* a, float v) {
    if (v >= 0.0f) atomicMin((int*)a, __float_as_int(v));
    else           atomicMax((unsigned int*)a, __float_as_uint(v));
}

// ---------------- kernel 0: init --------------------------------------------
__global__ void init_kernel() {
    g_min = INFINITY;
    g_max = -INFINITY;
    g_sum = 0.0;
}

// ---------------- kernel 1: global min/max of y_pred ------------------------
__global__ void minmax_kernel(const float4* __restrict__ x, int n4) {
    float vmin = INFINITY, vmax = -INFINITY;
    for (int i = blockIdx.x * blockDim.x + threadIdx.x; i < n4;
         i += gridDim.x * blockDim.x) {
        float4 v = x[i];
        vmin = fminf(vmin, fminf(fminf(v.x, v.y), fminf(v.z, v.w)));
        vmax = fmaxf(vmax, fmaxf(fmaxf(v.x, v.y), fmaxf(v.z, v.w)));
    }
    #pragma unroll
    for (int o = 16; o > 0; o >>= 1) {
        vmin = fminf(vmin, __shfl_down_sync(0xffffffffu, vmin, o));
        vmax = fmaxf(vmax, __shfl_down_sync(0xffffffffu, vmax, o));
    }
    __shared__ float smin[32], smax[32];
    int lane = threadIdx.x & 31, wid = threadIdx.x >> 5;
    if (lane == 0) { smin[wid] = vmin; smax[wid] = vmax; }
    __syncthreads();
    if (wid == 0) {
        int nw = (blockDim.x + 31) >> 5;
        vmin = (lane < nw) ? smin[lane] : INFINITY;
        vmax = (lane < nw) ? smax[lane] : -INFINITY;
        #pragma unroll
        for (int o = 16; o > 0; o >>= 1) {
            vmin = fminf(vmin, __shfl_down_sync(0xffffffffu, vmin, o));
            vmax = fmaxf(vmax, __shfl_down_sync(0xffffffffu, vmax, o));
        }
        if (lane == 0) { atomicMinF(&g_min, vmin); atomicMaxF(&g_max, vmax); }
    }
}

// ---------------- kernel 2: row-streaming separable SSIM --------------------
// One CTA = 512 threads = one column each, streaming a 64-output-row strip of
// one image. Vertical 11-tap FIR kept in registers (5 maps x 11 rolling accs);
// only vertically-blurred rows hit smem. Horizontal pass batches 4 rows with
// float4 smem loads (4 outputs/thread, sliding window in registers).
__global__ __launch_bounds__(512, 1)
void ssim_stream_kernel(const float* __restrict__ xg,
                        const float* __restrict__ yg) {
    const float W[11] = {GW0, GW1, GW2, GW3, GW4, GW5,
                         GW4, GW3, GW2, GW1, GW0};

    __shared__ float vb[4 * 5 * VBW];     // 4 rows x 5 maps, padded width
    __shared__ float warp_part[16];

    const int tid   = threadIdx.x;
    const int strip = blockIdx.x;
    const int img   = blockIdx.y;
    const int rows_base = strip * RSTRIP;
    const int nrows     = min(RSTRIP, OUT_H - rows_base);
    const int ngroups   = (nrows + 3) >> 2;

    const float* __restrict__ xi = xg + (size_t)img * (IMG_H * IMG_W);
    const float* __restrict__ yi = yg + (size_t)img * (IMG_H * IMG_W);

    const float L  = g_max - g_min;
    const float C1 = (0.01f * L) * (0.01f * L);
    const float C2 = (0.03f * L) * (0.03f * L);

    // rolling vertical accumulators: acc[j] ~ output row (cur_in_row-10+j)
    float a1[11], a2[11], axx[11], ayy[11], axy[11];
    #pragma unroll
    for (int j = 0; j < 11; j++) {
        a1[j] = a2[j] = axx[j] = ayy[j] = axy[j] = 0.0f;
    }

    // ---- prologue: input rows 0..9 (no flush) ----
    {
        float px[10], py[10];
        #pragma unroll
        for (int i = 0; i < 10; i++) {
            int idx = (rows_base + i) * IMG_W + tid;   // always in-bounds
            px[i] = xi[idx];
            py[i] = yi[idx];
        }
        #pragma unroll
        for (int i = 0; i < 10; i++) {
            float x = px[i], y = py[i];
            float xx = x * x, yy = y * y, xy = x * y;
            #pragma unroll
            for (int j = 0; j < 11; j++) {
                float w = W[10 - j];
                a1 [j] = fmaf(w, x,  a1 [j]);
                a2 [j] = fmaf(w, y,  a2 [j]);
                axx[j] = fmaf(w, xx, axx[j]);
                ayy[j] = fmaf(w, yy, ayy[j]);
                axy[j] = fmaf(w, xy, axy[j]);
            }
            #pragma unroll
            for (int j = 0; j < 10; j++) {
                a1[j] = a1[j+1]; a2[j] = a2[j+1];
                axx[j] = axx[j+1]; ayy[j] = ayy[j+1]; axy[j] = axy[j+1];
            }
            a1[10] = a2[10] = axx[10] = ayy[10] = axy[10] = 0.0f;
        }
    }

    const int hrow = tid >> 7;          // 0..3 : which of the 4 buffered rows
    const int c0   = (tid & 127) * 4;   // 0..508 : first output column
    float tsum = 0.0f;

    // preload group 0's input rows (rows 10..13, always in-bounds)
    float xv[4], yv[4];
    #pragma unroll
    for (int s = 0; s < 4; s++) {
        int idx = (rows_base + 10 + s) * IMG_W + tid;
        xv[s] = xi[idx];
        yv[s] = yi[idx];
    }

    for (int g = 0; g < ngroups; g++) {
        // ---- vertical FIR update + flush 4 rows into smem ----
        #pragma unroll
        for (int s = 0; s < 4; s++) {
            float x = xv[s], y = yv[s];
            float xx = x * x, yy = y * y, xy = x * y;
            #pragma unroll
            for (int j = 0; j < 11; j++) {
                float w = W[10 - j];
                a1 [j] = fmaf(w, x,  a1 [j]);
                a2 [j] = fmaf(w, y,  a2 [j]);
                axx[j] = fmaf(w, xx, axx[j]);
                ayy[j] = fmaf(w, yy, ayy[j]);
                axy[j] = fmaf(w, xy, axy[j]);
            }
            vb[(s * 5 + 0) * VBW + tid] = a1 [0];
            vb[(s * 5 + 1) * VBW + tid] = a2 [0];
            vb[(s * 5 + 2) * VBW + tid] = axx[0];
            vb[(s * 5 + 3) * VBW + tid] = ayy[0];
            vb[(s * 5 + 4) * VBW + tid] = axy[0];
            #pragma unroll
            for (int j = 0; j < 10; j++) {
                a1[j] = a1[j+1]; a2[j] = a2[j+1];
                axx[j] = axx[j+1]; ayy[j] = ayy[j+1]; axy[j] = axy[j+1];
            }
            a1[10] = a2[10] = axx[10] = ayy[10] = axy[10] = 0.0f;
        }
        __syncthreads();

        // ---- prefetch next group's input rows (hidden under horizontal) ----
        if (g + 1 < ngroups) {
            #pragma unroll
            for (int s = 0; s < 4; s++) {
                int gr = rows_base + (g + 1) * 4 + 10 + s;
                bool ok = gr < IMG_H;
                int idx = gr * IMG_W + tid;
                xv[s] = ok ? xi[idx] : 0.0f;
                yv[s] = ok ? yi[idx] : 0.0f;
            }
        }

        // ---- horizontal 11-tap + SSIM: 4 outputs per thread ----
        float h[5][4];
        #pragma unroll
        for (int m = 0; m < 5; m++) {
            const float4* p =
                (const float4*)&vb[(hrow * 5 + m) * VBW + c0];
            float4 q0 = p[0], q1 = p[1], q2 = p[2], q3 = p[3];
            float v[16] = {q0.x, q0.y, q0.z, q0.w, q1.x, q1.y, q1.z, q1.w,
                           q2.x, q2.y, q2.z, q2.w, q3.x, q3.y, q3.z, q3.w};
            #pragma unroll
            for (int off = 0; off < 4; off++) {
                float acc = 0.0f;
                #pragma unroll
                for (int k = 0; k < 11; k++)
                    acc = fmaf(W[k], v[off + k], acc);
                h[m][off] = acc;
            }
        }
        int orow = rows_base + g * 4 + hrow;
        if (orow < OUT_H) {
            #pragma unroll
            for (int off = 0; off < 4; off++) {
                int col = c0 + off;
                if (col < OUT_W) {
                    float mu1 = h[0][off], mu2 = h[1][off];
                    float mxx = h[2][off], myy = h[3][off], mxy = h[4][off];
                    float mu1sq = mu1 * mu1;
                    float mu2sq = mu2 * mu2;
                    float mu12  = mu1 * mu2;
                    float v1  = 2.0f * (mxy - mu12) + C2;
                    float v2  = (mxx - mu1sq) + (myy - mu2sq) + C2;
                    float num = (2.0f * mu12 + C1) * v1;
                    float den = (mu1sq + mu2sq + C1) * v2;
                    tsum += __fdividef(num, den);
                }
            }
        }
        __syncthreads();
    }

    // ---- block reduction into global double sum ----
    #pragma unroll
    for (int o = 16; o > 0; o >>= 1)
        tsum += __shfl_down_sync(0xffffffffu, tsum, o);
    int lane = tid & 31, wid = tid >> 5;
    if (lane == 0) warp_part[wid] = tsum;
    __syncthreads();
    if (wid == 0) {
        float v = (lane < 16) ? warp_part[lane] : 0.0f;
        #pragma unroll
        for (int o = 8; o > 0; o >>= 1)
            v += __shfl_down_sync(0xffffffffu, v, o);
        if (lane == 0) atomicAdd(&g_sum, (double)v);
    }
}

// ---------------- kernel 3: finalize ----------------------------------------
__global__ void finalize_kernel(float* __restrict__ out) {
    const double n = (double)N_IMG * OUT_H * OUT_W;
    out[0] = (float)(-(g_sum / n));
}

// ---------------- launcher ---------------------------------------------------
extern "C" void kernel_launch(void* const* d_in, const int* in_sizes, int n_in,
                              void* d_out, int out_size) {
    const float* y_pred = (const float*)d_in[0];
    const float* y_true = (const float*)d_in[1];
    float* out = (float*)d_out;

    init_kernel<<<1, 1>>>();

    int n4 = (N_IMG * IMG_H * IMG_W) / 4;
    minmax_kernel<<<1024, 256>>>((const float4*)y_pred, n4);

    dim3 grid(NSTRIPS, N_IMG);
    ssim_stream_kernel<<<grid, 512>>>(y_pred, y_true);

    finalize_kernel<<<1, 1>>>(out);
}